// round 8
// baseline (speedup 1.0000x reference)
#include <cuda_runtime.h>
#include <cuda_bf16.h>
#include <math.h>
#include <stdint.h>

// Problem constants
#define BB 4
#define SS 2048
#define EE 1024
#define HH 8
#define DD 128
#define TT (BB*SS)          // 8192 tokens
#define EPSF 1e-5f

// ---------------- scratch (device globals) ----------------------------------
__device__ float g_Z  [TT*EE];
__device__ float g_HLN[TT*EE];
__device__ float g_H1 [TT*EE];
__device__ float g_G  [TT*EE];
__device__ float g_P  [TT*EE];
__device__ float g_LG [TT*HH];
__device__ float g_SC [TT*HH];
__device__ float g_V  [HH*DD];
__device__ float g_C  [HH];
__device__ float g_WezT[EE*EE];    // W_ez^T  [n][k]
__device__ float g_W2T [EE*EE];    // ff_W2^T [n][k]
__device__ float g_W1T [HH*DD*DD]; // per-head W1^T [h][e][d]

// ---------------- helpers ----------------------------------------------------
__device__ __forceinline__ uint32_t smem_u32(const void* p) {
    uint32_t a;
    asm("{ .reg .u64 t; cvta.to.shared.u64 t, %1; cvt.u32.u64 %0, t; }"
        : "=r"(a) : "l"(p));
    return a;
}
#define LDSM4(r0, r1, r2, r3, a) \
    asm volatile("ldmatrix.sync.aligned.m8n8.x4.shared.b16 {%0,%1,%2,%3}, [%4];" \
        : "=r"(r0), "=r"(r1), "=r"(r2), "=r"(r3) : "r"(a))
#define LDSM2(r0, r1, a) \
    asm volatile("ldmatrix.sync.aligned.m8n8.x2.shared.b16 {%0,%1}, [%2];" \
        : "=r"(r0), "=r"(r1) : "r"(a))

__device__ __forceinline__ void mmabf(float* c, const uint32_t* a, const uint32_t* b) {
    asm volatile("mma.sync.aligned.m16n8k16.row.col.f32.bf16.bf16.f32 "
        "{%0,%1,%2,%3}, {%4,%5,%6,%7}, {%8,%9}, {%0,%1,%2,%3};"
        : "+f"(c[0]), "+f"(c[1]), "+f"(c[2]), "+f"(c[3])
        : "r"(a[0]), "r"(a[1]), "r"(a[2]), "r"(a[3]), "r"(b[0]), "r"(b[1]));
}

__device__ __forceinline__ float ex2_(float x) {
    float y; asm("ex2.approx.f32 %0, %1;" : "=f"(y) : "f"(x)); return y;
}
__device__ __forceinline__ float rcp_(float x) {
    float y; asm("rcp.approx.f32 %0, %1;" : "=f"(y) : "f"(x)); return y;
}

// radix-4 butterfly reduce of two values over 32 lanes (3 levels)
__device__ __forceinline__ void r4red2(float& x, float& y) {
    float a1 = __shfl_xor_sync(0xffffffffu, x, 1);
    float b1 = __shfl_xor_sync(0xffffffffu, y, 1);
    float a2 = __shfl_xor_sync(0xffffffffu, x, 2);
    float b2 = __shfl_xor_sync(0xffffffffu, y, 2);
    float a3 = __shfl_xor_sync(0xffffffffu, x, 3);
    float b3 = __shfl_xor_sync(0xffffffffu, y, 3);
    x = (x + a1) + (a2 + a3);
    y = (y + b1) + (b2 + b3);
    a1 = __shfl_xor_sync(0xffffffffu, x, 4);
    b1 = __shfl_xor_sync(0xffffffffu, y, 4);
    a2 = __shfl_xor_sync(0xffffffffu, x, 8);
    b2 = __shfl_xor_sync(0xffffffffu, y, 8);
    a3 = __shfl_xor_sync(0xffffffffu, x, 12);
    b3 = __shfl_xor_sync(0xffffffffu, y, 12);
    x = (x + a1) + (a2 + a3);
    y = (y + b1) + (b2 + b3);
    x += __shfl_xor_sync(0xffffffffu, x, 16);
    y += __shfl_xor_sync(0xffffffffu, y, 16);
}

// split 8 fp32 into hi (truncated bf16) + mid (bf16 residual), packed bf16x2
__device__ __forceinline__ void split_store8(float4 u, float4 v,
                                             char* hiP, char* miP)
{
    const uint32_t e0 = __float_as_uint(u.x), e1 = __float_as_uint(u.y);
    const uint32_t e2 = __float_as_uint(u.z), e3 = __float_as_uint(u.w);
    const uint32_t e4 = __float_as_uint(v.x), e5 = __float_as_uint(v.y);
    const uint32_t e6 = __float_as_uint(v.z), e7 = __float_as_uint(v.w);

    uint4 hi;
    hi.x = __byte_perm(e0, e1, 0x7632);
    hi.y = __byte_perm(e2, e3, 0x7632);
    hi.z = __byte_perm(e4, e5, 0x7632);
    hi.w = __byte_perm(e6, e7, 0x7632);

    const float m0 = u.x - __uint_as_float(e0 & 0xFFFF0000u);
    const float m1 = u.y - __uint_as_float(e1 & 0xFFFF0000u);
    const float m2 = u.z - __uint_as_float(e2 & 0xFFFF0000u);
    const float m3 = u.w - __uint_as_float(e3 & 0xFFFF0000u);
    const float m4 = v.x - __uint_as_float(e4 & 0xFFFF0000u);
    const float m5 = v.y - __uint_as_float(e5 & 0xFFFF0000u);
    const float m6 = v.z - __uint_as_float(e6 & 0xFFFF0000u);
    const float m7 = v.w - __uint_as_float(e7 & 0xFFFF0000u);

    uint4 mi;
    __nv_bfloat162 t;
    t = __floats2bfloat162_rn(m0, m1); mi.x = *(uint32_t*)&t;
    t = __floats2bfloat162_rn(m2, m3); mi.y = *(uint32_t*)&t;
    t = __floats2bfloat162_rn(m4, m5); mi.z = *(uint32_t*)&t;
    t = __floats2bfloat162_rn(m6, m7); mi.w = *(uint32_t*)&t;

    *(uint4*)hiP = hi;
    *(uint4*)miP = mi;
}

// ---------------- transposes -------------------------------------------------
__global__ void transpose1024(const float* __restrict__ in, float* __restrict__ out)
{
    __shared__ float tile[32][33];
    const int x = blockIdx.x*32 + threadIdx.x;
    const int y = blockIdx.y*32 + threadIdx.y;
    #pragma unroll
    for (int j = 0; j < 32; j += 8)
        tile[threadIdx.y + j][threadIdx.x] = in[(size_t)(y + j)*EE + x];
    __syncthreads();
    const int x2 = blockIdx.y*32 + threadIdx.x;
    const int y2 = blockIdx.x*32 + threadIdx.y;
    #pragma unroll
    for (int j = 0; j < 32; j += 8)
        out[(size_t)(y2 + j)*EE + x2] = tile[threadIdx.x][threadIdx.y + j];
}

__global__ void transpose_w1(const float* __restrict__ in, float* __restrict__ out)
{
    __shared__ float tile[32][33];
    const int h = blockIdx.z;
    const size_t base = (size_t)h*DD*DD;
    const int x = blockIdx.x*32 + threadIdx.x;
    const int y = blockIdx.y*32 + threadIdx.y;
    #pragma unroll
    for (int j = 0; j < 32; j += 8)
        tile[threadIdx.y + j][threadIdx.x] = in[base + (size_t)(y + j)*DD + x];
    __syncthreads();
    const int x2 = blockIdx.y*32 + threadIdx.x;
    const int y2 = blockIdx.x*32 + threadIdx.y;
    #pragma unroll
    for (int j = 0; j < 32; j += 8)
        out[base + (size_t)(y2 + j)*DD + x2] = tile[threadIdx.x][threadIdx.y + j];
}

// ---------------- prep_v: one warp per output dot product -------------------
__global__ void prep_v2(const float* __restrict__ W2,
                        const float* __restrict__ b2,
                        const float* __restrict__ watt)
{
    const int w    = threadIdx.x >> 5;
    const int lane = threadIdx.x & 31;
    const float* rp;
    if (blockIdx.x < 128) rp = W2 + (size_t)(blockIdx.x*8 + w)*EE;
    else                  rp = b2 + (size_t)w*EE;
    float s = 0.f;
    #pragma unroll
    for (int j = 0; j < 8; j++) {
        const float4 a  = *(const float4*)(rp   + lane*4 + j*128);
        const float4 wv = *(const float4*)(watt + lane*4 + j*128);
        s = fmaf(a.x, wv.x, fmaf(a.y, wv.y, fmaf(a.z, wv.z, fmaf(a.w, wv.w, s))));
    }
    #pragma unroll
    for (int off = 16; off >= 1; off >>= 1)
        s += __shfl_xor_sync(0xffffffffu, s, off);
    if (lane == 0) {
        if (blockIdx.x < 128) g_V[blockIdx.x*8 + w] = s;
        else                  g_C[w] = s;
    }
}

// ======= split-bf16 3-pass GEMM via mma.m16n8k16 + ldmatrix ==================
// CTA 128x128, 8 warps (2m x 4n), warp tile 64x32; double-buffered smem.
// EPI==0: g_Z = tanh(x @ WezT^T + b_ez)              (K=1024)
// EPI==1: g_H1 = gelu(hln @ W1T[h]^T + b1); logits   (K=128, blockIdx.z = h)
// EPI==2: g_P = g_G @ W2T^T + sum_h scores*b2        (K=1024)
#define PL   6144           // plane bytes (128 * 48)
#define STG  (4*PL)         // stage bytes  (24576)
template<int EPI>
__global__ void __launch_bounds__(256, 2) bf_gemm(
    const float* __restrict__ Aext, const float* __restrict__ Btg,
    const float* __restrict__ bias)
{
    extern __shared__ char smq[];   // 2 * STG = 49152 bytes
    __shared__ float slog[128];

    const int h = (EPI==1) ? (int)blockIdx.z : 0;
    const float* A  = (EPI==0) ? Aext : (EPI==1) ? (g_HLN + h*DD) : g_G;
    const float* Bt = (EPI==1) ? (g_W1T + (size_t)h*DD*DD) : Btg;
    float*       C  = (EPI==0) ? g_Z  : (EPI==1) ? g_H1 : g_P;
    const int LDB = (EPI==1) ? DD : EE;
    const int NKT = (EPI==1) ? 8 : 64;

    const int tid  = threadIdx.x;
    const int wid  = tid >> 5;
    const int lane = tid & 31;
    const int wm   = wid >> 2;      // 0..1
    const int wn   = wid & 3;       // 0..3
    const int rr   = lane & 7;
    const int mq   = lane >> 3;     // 0..3
    const int r    = lane >> 2;     // 0..7
    const int cq   = lane & 3;      // 0..3

    const int m0 = blockIdx.y * 128;
    const int n0 = (EPI==1) ? 0 : blockIdx.x * 128;
    const int colBase = (EPI==1) ? h*DD : n0;

    // producer mapping: thread -> (row 0..127, half 0/1 of 16 k's)
    const int prow = tid >> 1;
    const int phalf = tid & 1;
    const float* srcA = A  + (size_t)(m0 + prow)*EE + phalf*8;
    const float* srcB = Bt + (size_t)(n0 + prow)*LDB + phalf*8;
    char* pdst = smq + prow*48 + phalf*16;

    // consumer ldmatrix lane addresses (within stage)
    const uint32_t sb = smem_u32(smq);
    const uint32_t aAddr = sb + (uint32_t)((wm*64 + (mq&1)*8 + rr)*48 + (mq>>1)*16);
    const uint32_t bAddr = sb + 2u*PL + (uint32_t)((wn*32 + rr)*48 + (mq&1)*16);

    // prologue: chunk 0
    {
        float4 a0 = *(const float4*)(srcA);
        float4 a1 = *(const float4*)(srcA + 4);
        float4 b0 = *(const float4*)(srcB);
        float4 b1 = *(const float4*)(srcB + 4);
        split_store8(a0, a1, pdst,        pdst + PL);
        split_store8(b0, b1, pdst + 2*PL, pdst + 3*PL);
    }
    if (EPI == 1 && tid < 128) slog[tid] = 0.f;
    __syncthreads();

    float acc[4][4][4];
    #pragma unroll
    for (int i = 0; i < 4; i++)
        #pragma unroll
        for (int j = 0; j < 4; j++)
            #pragma unroll
            for (int q = 0; q < 4; q++) acc[i][j][q] = 0.f;

    #pragma unroll 1
    for (int kt = 0; kt < NKT; kt++) {
        float4 pa0, pa1, pb0, pb1;
        if (kt + 1 < NKT) {
            const int ko = (kt + 1) * 16;
            pa0 = *(const float4*)(srcA + ko);
            pa1 = *(const float4*)(srcA + ko + 4);
            pb0 = *(const float4*)(srcB + ko);
            pb1 = *(const float4*)(srcB + ko + 4);
        }

        const uint32_t st = (kt & 1) * (uint32_t)STG;

        uint32_t bh[4][2], bm[4][2];
        #pragma unroll
        for (int ni = 0; ni < 4; ni++) {
            LDSM2(bh[ni][0], bh[ni][1], bAddr + st + ni*384);
            LDSM2(bm[ni][0], bm[ni][1], bAddr + st + PL + ni*384);
        }

        #pragma unroll
        for (int mi = 0; mi < 4; mi++) {
            uint32_t ah[4], am[4];
            LDSM4(ah[0], ah[1], ah[2], ah[3], aAddr + st + mi*768);
            LDSM4(am[0], am[1], am[2], am[3], aAddr + st + PL + mi*768);
            #pragma unroll
            for (int ni = 0; ni < 4; ni++) mmabf(acc[mi][ni], ah, bh[ni]);
            #pragma unroll
            for (int ni = 0; ni < 4; ni++) mmabf(acc[mi][ni], ah, bm[ni]);
            #pragma unroll
            for (int ni = 0; ni < 4; ni++) mmabf(acc[mi][ni], am, bh[ni]);
        }

        if (kt + 1 < NKT) {
            char* nd = pdst + (((kt + 1) & 1) ? STG : 0);
            split_store8(pa0, pa1, nd,        nd + PL);
            split_store8(pb0, pb1, nd + 2*PL, nd + 3*PL);
        }
        __syncthreads();
    }

    // ---------------- epilogue ----------------
    #pragma unroll
    for (int mi = 0; mi < 4; mi++) {
        const int row0 = m0 + wm*64 + mi*16 + r;    // and row0+8
        float sAr[8], sBr[8];
        if (EPI == 2) {
            #pragma unroll
            for (int h2 = 0; h2 < 8; h2++) {
                sAr[h2] = g_SC[(size_t)row0*8 + h2];
                sBr[h2] = g_SC[(size_t)(row0+8)*8 + h2];
            }
        }
        float logitA = 0.f, logitB = 0.f;
        #pragma unroll
        for (int ni = 0; ni < 4; ni++) {
            const int col = colBase + wn*32 + ni*8 + 2*cq;
            float v0 = acc[mi][ni][0], v1 = acc[mi][ni][1];
            float v2 = acc[mi][ni][2], v3 = acc[mi][ni][3];
            if (EPI == 0) {
                v0 = tanhf(v0 + bias[col]);
                v1 = tanhf(v1 + bias[col+1]);
                v2 = tanhf(v2 + bias[col]);
                v3 = tanhf(v3 + bias[col+1]);
            } else if (EPI == 1) {
                const float b0 = bias[col], b1 = bias[col+1];
                v0 += b0; v1 += b1; v2 += b0; v3 += b1;
                v0 = 0.5f*v0*(1.f + erff(v0*0.70710678118654752f));
                v1 = 0.5f*v1*(1.f + erff(v1*0.70710678118654752f));
                v2 = 0.5f*v2*(1.f + erff(v2*0.70710678118654752f));
                v3 = 0.5f*v3*(1.f + erff(v3*0.70710678118654752f));
                const float w0 = g_V[col], w1 = g_V[col+1];
                logitA = fmaf(v0, w0, fmaf(v1, w1, logitA));
                logitB = fmaf(v2, w0, fmaf(v3, w1, logitB));
            } else {
                float b00=0.f, b01=0.f, b10=0.f, b11=0.f;
                #pragma unroll
                for (int h2 = 0; h2 < 8; h2++) {
                    const float w0 = bias[(size_t)h2*EE + col];
                    const float w1 = bias[(size_t)h2*EE + col + 1];
                    b00 = fmaf(sAr[h2], w0, b00);
                    b01 = fmaf(sAr[h2], w1, b01);
                    b10 = fmaf(sBr[h2], w0, b10);
                    b11 = fmaf(sBr[h2], w1, b11);
                }
                v0 += b00; v1 += b01; v2 += b10; v3 += b11;
            }
            float2 p0; p0.x = v0; p0.y = v1;
            float2 p1; p1.x = v2; p1.y = v3;
            *(float2*)(C + (size_t)row0*EE + col)     = p0;
            *(float2*)(C + (size_t)(row0+8)*EE + col) = p1;
        }
        if (EPI == 1) {
            logitA += __shfl_xor_sync(0xffffffffu, logitA, 1);
            logitA += __shfl_xor_sync(0xffffffffu, logitA, 2);
            logitB += __shfl_xor_sync(0xffffffffu, logitB, 1);
            logitB += __shfl_xor_sync(0xffffffffu, logitB, 2);
            if (cq == 0) {
                atomicAdd(&slog[row0 - m0],     logitA);
                atomicAdd(&slog[row0 - m0 + 8], logitB);
            }
        }
    }

    if (EPI == 1) {
        __syncthreads();
        if (tid < 128)
            g_LG[(size_t)(m0 + tid)*8 + h] = slog[tid] + g_C[h];
    }
}

// ---------------- fused scan: gated recurrence + step LN + head LN ----------
// One warp per (b,h); 4 d's per lane. The os_diag-LN of step s-1 executes in
// the latency shadow of step s's sigmoid chain. Writes g_HLN directly.
__global__ void scan_kernel(const float* __restrict__ Uh,
                            const float* __restrict__ Uz,
                            const float* __restrict__ Bu,
                            const float* __restrict__ Lg,
                            const float* __restrict__ Lb,
                            const float* __restrict__ OS,
                            const float* __restrict__ Fg,
                            const float* __restrict__ Fb)
{
    const int bidx = blockIdx.x;
    const int b  = bidx >> 3;
    const int hh = bidx & 7;
    const int lane = threadIdx.x;
    const float G = -1.4426950408889634f;   // -log2(e)

    float A[4], uzs[4], busr[4], bus2[4], lg[4], lb[4], osd[4], fg[4], fb[4];
    #pragma unroll
    for (int i = 0; i < 4; i++) {
        const int d = lane + 32*i;
        const float uh = Uh[(size_t)hh*DD*DD + (size_t)d*(DD+1)];
        const float uz = Uz[(size_t)hh*DD*DD + (size_t)d*(DD+1)];
        const float bu = Bu[hh*DD + d];
        lg[i] = Lg[d];  lb[i] = Lb[d];
        A[i]    = G*uh*lg[i];
        uzs[i]  = G*uz;
        busr[i] = G*bu;                 // step-0 (h=0) variant
        bus2[i] = G*bu + G*uh*lb[i];    // folded lb term for steps >= 1
        osd[i]  = OS[(size_t)hh*DD*DD + (size_t)d*(DD+1)];
        fg[i]   = Fg[hh*DD + d];
        fb[i]   = Fb[hh*DD + d];
    }

    const float* zp = g_Z   + (size_t)b*SS*EE + hh*DD + lane;
    float*       op = g_HLN + (size_t)b*SS*EE + hh*DD + lane;

    float z0[4], z1[4], z2[4];
    #pragma unroll
    for (int i = 0; i < 4; i++) z0[i] = zp[32*i];
    #pragma unroll
    for (int i = 0; i < 4; i++) z1[i] = zp[1024 + 32*i];
    #pragma unroll
    for (int i = 0; i < 4; i++) z2[i] = zp[2048 + 32*i];

    float hnP[4];   // normalized (pre-affine) state of previous step
    float oP[4];    // affine state h of previous step

    // -------- peel step 0 (h_prev = 0) --------
    {
        float s1 = 0.f, s2 = 0.f, hn[4];
        #pragma unroll
        for (int i = 0; i < 4; i++) {
            const float e = ex2_(fmaf(z0[i], uzs[i], busr[i]));
            const float u = rcp_(1.f + e);
            const float v = z0[i] - u*z0[i];      // u*0 + (1-u)*z
            hn[i] = v;
            s1 += v;
            s2 = fmaf(v, v, s2);
        }
        r4red2(s1, s2);
        const float mean = s1 * (1.f/128.f);
        const float var  = fmaf(s2, 1.f/128.f, -mean*mean);
        const float rstd = rsqrtf(var + EPSF);
        #pragma unroll
        for (int i = 0; i < 4; i++) {
            hnP[i] = (hn[i] - mean) * rstd;
            oP[i]  = fmaf(hnP[i], lg[i], lb[i]);
        }
    }

    float zz[4];
    #pragma unroll
    for (int i = 0; i < 4; i++) zz[i] = fmaf(z1[i], uzs[i], bus2[i]);
    // shift: z0 <- z[1], z1 <- z[2]
    #pragma unroll
    for (int i = 0; i < 4; i++) { z0[i] = z1[i]; z1[i] = z2[i]; }

    for (int s = 1; s < SS; s++) {
        // ---- launch critical chain of step s ----
        float e[4], hz[4];
        #pragma unroll
        for (int i = 0; i < 4; i++)
            e[i] = ex2_(fmaf(hnP[i], A[i], zz[i]));
        #pragma unroll
        for (int i = 0; i < 4; i++)
            hz[i] = oP[i] - z0[i];

        // ---- head-LN of step s-1 (in the sigmoid shadow) ----
        {
            float y[4], t1 = 0.f, t2 = 0.f;
            #pragma unroll
            for (int i = 0; i < 4; i++) {
                y[i] = oP[i] * osd[i];
                t1 += y[i];
                t2 = fmaf(y[i], y[i], t2);
            }
            r4red2(t1, t2);
            const float m2 = t1 * (1.f/128.f);
            const float v2v = fmaf(t2, 1.f/128.f, -m2*m2);
            const float r2 = rsqrtf(v2v + EPSF);
            float* so = op + (size_t)(s-1)*EE;
            #pragma unroll
            for (int i = 0; i < 4; i++)
                so[32*i] = fmaf((y[i] - m2)*r2, fg[i], fb[i]);
        }

        // prefetch z[s+2]
        #pragma unroll
        for (int i = 0; i < 4; i++) z2[i] = 0.f;
        if (s + 2 < SS) {
            const float* p = zp + (size_t)(s+2)*EE;
            #pragma unroll
            for (int i = 0; i < 4; i++) z2[i] = p[32*i];
        }

        // ---- finish gate + state update ----
        float s1 = 0.f, s2 = 0.f, hn[4];
        #pragma unroll
        for (int i = 0; i < 4; i++) {
            const float u = rcp_(1.f + e[i]);
            const float v = fmaf(u, hz[i], z0[i]);
            hn[i] = v;
            s1 += v;
            s2 = fmaf(v, v, s2);
        }
        // next step's z-part (independent; issues in the reduce shadow)
        float zzn[4];
        #pragma unroll
        for (int i = 0; i < 4; i++) zzn[i] = fmaf(z1[i], uzs[i], bus2[i]);

        r4red2(s1, s2);
        const float mean = s1 * (1.f/128.f);
        const float var  = fmaf(s2, 1.f/128.f, -mean*mean);
        const float rstd = rsqrtf(var + EPSF);
        #pragma unroll
        for (int i = 0; i < 4; i++) {
            hnP[i] = (hn[i] - mean) * rstd;
            oP[i]  = fmaf(hnP[i], lg[i], lb[i]);
        }
        #pragma unroll
        for (int i = 0; i < 4; i++) { z0[i] = z1[i]; z1[i] = z2[i]; zz[i] = zzn[i]; }
    }

    // ---- head-LN of the final step ----
    {
        float y[4], t1 = 0.f, t2 = 0.f;
        #pragma unroll
        for (int i = 0; i < 4; i++) {
            y[i] = oP[i] * osd[i];
            t1 += y[i];
            t2 = fmaf(y[i], y[i], t2);
        }
        r4red2(t1, t2);
        const float m2 = t1 * (1.f/128.f);
        const float v2v = fmaf(t2, 1.f/128.f, -m2*m2);
        const float r2 = rsqrtf(v2v + EPSF);
        float* so = op + (size_t)(SS-1)*EE;
        #pragma unroll
        for (int i = 0; i < 4; i++)
            so[32*i] = fmaf((y[i] - m2)*r2, fg[i], fb[i]);
    }
}

// ---------------- softmax over heads + scale h1 -> g ------------------------
__global__ void softmax_scale()
{
    const int t    = blockIdx.x*8 + (threadIdx.x >> 5);
    const int lane = threadIdx.x & 31;

    float l[8];
    #pragma unroll
    for (int h2 = 0; h2 < 8; h2++) l[h2] = g_LG[(size_t)t*8 + h2];
    float m = l[0];
    #pragma unroll
    for (int h2 = 1; h2 < 8; h2++) m = fmaxf(m, l[h2]);
    float ssum = 0.f;
    #pragma unroll
    for (int h2 = 0; h2 < 8; h2++) { l[h2] = __expf(l[h2]-m); ssum += l[h2]; }
    const float inv = __fdividef(1.f, ssum);

    const float4* in  = (const float4*)(g_H1 + (size_t)t*1024);
    float4*       out = (float4*)      (g_G  + (size_t)t*1024);
    #pragma unroll
    for (int i = 0; i < 8; i++) {
        const float sh = l[i]*inv;
        float4 v = in[i*32 + lane];
        v.x *= sh; v.y *= sh; v.z *= sh; v.w *= sh;
        out[i*32 + lane] = v;
    }
    if (lane < 8) g_SC[(size_t)t*8 + lane] = l[lane]*inv;
}

// ---------------- final LN over E -------------------------------------------
__global__ void final_ln(const float* __restrict__ lg_,
                         const float* __restrict__ lb_,
                         float* __restrict__ out)
{
    __shared__ float sm[16];
    const int t   = blockIdx.x;
    const int tid = threadIdx.x;

    const float4 v = ((const float4*)(g_P + (size_t)t*1024))[tid];
    float s1 = (v.x+v.y)+(v.z+v.w);
    float s2 = fmaf(v.x,v.x, fmaf(v.y,v.y, fmaf(v.z,v.z, v.w*v.w)));
    #pragma unroll
    for (int off = 16; off >= 1; off >>= 1) {
        s1 += __shfl_xor_sync(0xffffffffu, s1, off);
        s2 += __shfl_xor_sync(0xffffffffu, s2, off);
    }
    const int w = tid >> 5, lane = tid & 31;
    if (lane == 0) { sm[w] = s1; sm[8+w] = s2; }
    __syncthreads();
    float t1 = 0.f, t2 = 0.f;
    #pragma unroll
    for (int w2 = 0; w2 < 8; w2++) { t1 += sm[w2]; t2 += sm[8+w2]; }
    const float mean = t1 * (1.f/1024.f);
    const float var  = fmaf(t2, 1.f/1024.f, -mean*mean);
    const float rstd = rsqrtf(var + EPSF);

    const float4 g4 = ((const float4*)lg_)[tid];
    const float4 b4 = ((const float4*)lb_)[tid];
    float4 o;
    o.x = fmaf((v.x-mean)*rstd, g4.x, b4.x);
    o.y = fmaf((v.y-mean)*rstd, g4.y, b4.y);
    o.z = fmaf((v.z-mean)*rstd, g4.z, b4.z);
    o.w = fmaf((v.w-mean)*rstd, g4.w, b4.w);
    ((float4*)(out + (size_t)t*1024))[tid] = o;
}

// ---------------- launch ----------------------------------------------------
#define GEMM_SMEM (2*STG)   // 49152 bytes

extern "C" void kernel_launch(void* const* d_in, const int* in_sizes, int n_in,
                              void* d_out, int out_size)
{
    const float* x      = (const float*)d_in[0];
    const float* W_ez   = (const float*)d_in[1];
    const float* b_ez   = (const float*)d_in[2];
    const float* U_h    = (const float*)d_in[3];
    const float* U_z    = (const float*)d_in[4];
    const float* b_u    = (const float*)d_in[5];
    const float* out_sh = (const float*)d_in[6];
    const float* lns_g  = (const float*)d_in[7];
    const float* lns_b  = (const float*)d_in[8];
    const float* ffln_g = (const float*)d_in[9];
    const float* ffln_b = (const float*)d_in[10];
    const float* ff_W1  = (const float*)d_in[11];
    const float* ff_b1  = (const float*)d_in[12];
    const float* ff_W2  = (const float*)d_in[13];
    const float* ff_b2  = (const float*)d_in[14];
    const float* w_att  = (const float*)d_in[15];
    // d_in[16] = b_att: cancels in softmax
    const float* lno_g  = (const float*)d_in[17];
    const float* lno_b  = (const float*)d_in[18];
    float* out = (float*)d_out;

    cudaFuncSetAttribute(bf_gemm<0>, cudaFuncAttributeMaxDynamicSharedMemorySize, GEMM_SMEM);
    cudaFuncSetAttribute(bf_gemm<1>, cudaFuncAttributeMaxDynamicSharedMemorySize, GEMM_SMEM);
    cudaFuncSetAttribute(bf_gemm<2>, cudaFuncAttributeMaxDynamicSharedMemorySize, GEMM_SMEM);

    float* wezT; cudaGetSymbolAddress((void**)&wezT, g_WezT);
    float* w2T;  cudaGetSymbolAddress((void**)&w2T,  g_W2T);
    float* w1T;  cudaGetSymbolAddress((void**)&w1T,  g_W1T);

    // prep (independent, all fast)
    transpose1024<<<dim3(32,32), dim3(32,8)>>>(W_ez, wezT);
    transpose1024<<<dim3(32,32), dim3(32,8)>>>(ff_W2, w2T);
    transpose_w1<<<dim3(4,4,8), dim3(32,8)>>>(ff_W1, w1T);
    prep_v2<<<129, 256>>>(ff_W2, ff_b2, w_att);

    // z = tanh(x @ W_ez + b_ez)
    bf_gemm<0><<<dim3(EE/128, TT/128), 256, GEMM_SMEM>>>(x, wezT, b_ez);

    // fused scan (recurrence + step LN + head LN) -> g_HLN
    scan_kernel<<<BB*HH, 32>>>(U_h, U_z, b_u, lns_g, lns_b,
                               out_sh, ffln_g, ffln_b);

    // h1 = gelu(hln @ W1[h] + b1[h]); logits in epilogue
    bf_gemm<1><<<dim3(1, TT/128, HH), 256, GEMM_SMEM>>>(nullptr, nullptr, ff_b1);

    // softmax over heads; g = score * h1
    softmax_scale<<<TT/8, 256>>>();

    // weighted = g @ W2 + sum_h s_h*b2
    bf_gemm<2><<<dim3(EE/128, TT/128), 256, GEMM_SMEM>>>(nullptr, w2T, ff_b2);

    // final LN -> output
    final_ln<<<TT, 256>>>(lno_g, lno_b, out);
}

// round 11
// speedup vs baseline: 1.2247x; 1.2247x over previous
#include <cuda_runtime.h>
#include <cuda_bf16.h>
#include <math.h>
#include <stdint.h>

// Problem constants
#define BB 4
#define SS 2048
#define EE 1024
#define HH 8
#define DD 128
#define TT (BB*SS)          // 8192 tokens
#define EPSF 1e-5f

// ---------------- scratch (device globals) ----------------------------------
__device__ float g_Z  [TT*EE];
__device__ float g_ST [TT*EE];
__device__ float g_HLN[TT*EE];
__device__ float g_H1 [TT*EE];
__device__ float g_G  [TT*EE];
__device__ float g_P  [TT*EE];
__device__ float g_LG [TT*HH];
__device__ float g_SC [TT*HH];
__device__ float g_V  [HH*DD];
__device__ float g_C  [HH];
__device__ float g_WezT[EE*EE];    // W_ez^T  [n][k]
__device__ float g_W2T [EE*EE];    // ff_W2^T [n][k]
__device__ float g_W1T [HH*DD*DD]; // per-head W1^T [h][e][d]

// ---------------- helpers ----------------------------------------------------
__device__ __forceinline__ uint32_t smem_u32(const void* p) {
    uint32_t a;
    asm("{ .reg .u64 t; cvta.to.shared.u64 t, %1; cvt.u32.u64 %0, t; }"
        : "=r"(a) : "l"(p));
    return a;
}
#define LDSM4(r0, r1, r2, r3, a) \
    asm volatile("ldmatrix.sync.aligned.m8n8.x4.shared.b16 {%0,%1,%2,%3}, [%4];" \
        : "=r"(r0), "=r"(r1), "=r"(r2), "=r"(r3) : "r"(a))
#define LDSM2(r0, r1, a) \
    asm volatile("ldmatrix.sync.aligned.m8n8.x2.shared.b16 {%0,%1}, [%2];" \
        : "=r"(r0), "=r"(r1) : "r"(a))

__device__ __forceinline__ void mmabf(float* c, const uint32_t* a, const uint32_t* b) {
    asm volatile("mma.sync.aligned.m16n8k16.row.col.f32.bf16.bf16.f32 "
        "{%0,%1,%2,%3}, {%4,%5,%6,%7}, {%8,%9}, {%0,%1,%2,%3};"
        : "+f"(c[0]), "+f"(c[1]), "+f"(c[2]), "+f"(c[3])
        : "r"(a[0]), "r"(a[1]), "r"(a[2]), "r"(a[3]), "r"(b[0]), "r"(b[1]));
}

__device__ __forceinline__ float ex2_(float x) {
    float y; asm("ex2.approx.f32 %0, %1;" : "=f"(y) : "f"(x)); return y;
}
__device__ __forceinline__ float rcp_(float x) {
    float y; asm("rcp.approx.f32 %0, %1;" : "=f"(y) : "f"(x)); return y;
}

// radix-4 butterfly reduce of two values over 32 lanes (3 levels)
__device__ __forceinline__ void r4red2(float& x, float& y) {
    float a1 = __shfl_xor_sync(0xffffffffu, x, 1);
    float b1 = __shfl_xor_sync(0xffffffffu, y, 1);
    float a2 = __shfl_xor_sync(0xffffffffu, x, 2);
    float b2 = __shfl_xor_sync(0xffffffffu, y, 2);
    float a3 = __shfl_xor_sync(0xffffffffu, x, 3);
    float b3 = __shfl_xor_sync(0xffffffffu, y, 3);
    x = (x + a1) + (a2 + a3);
    y = (y + b1) + (b2 + b3);
    a1 = __shfl_xor_sync(0xffffffffu, x, 4);
    b1 = __shfl_xor_sync(0xffffffffu, y, 4);
    a2 = __shfl_xor_sync(0xffffffffu, x, 8);
    b2 = __shfl_xor_sync(0xffffffffu, y, 8);
    a3 = __shfl_xor_sync(0xffffffffu, x, 12);
    b3 = __shfl_xor_sync(0xffffffffu, y, 12);
    x = (x + a1) + (a2 + a3);
    y = (y + b1) + (b2 + b3);
    x += __shfl_xor_sync(0xffffffffu, x, 16);
    y += __shfl_xor_sync(0xffffffffu, y, 16);
}

// split 8 fp32 into hi (truncated bf16) + mid (bf16 residual), packed bf16x2
__device__ __forceinline__ void split_store8(float4 u, float4 v,
                                             char* hiP, char* miP)
{
    const uint32_t e0 = __float_as_uint(u.x), e1 = __float_as_uint(u.y);
    const uint32_t e2 = __float_as_uint(u.z), e3 = __float_as_uint(u.w);
    const uint32_t e4 = __float_as_uint(v.x), e5 = __float_as_uint(v.y);
    const uint32_t e6 = __float_as_uint(v.z), e7 = __float_as_uint(v.w);

    uint4 hi;
    hi.x = __byte_perm(e0, e1, 0x7632);
    hi.y = __byte_perm(e2, e3, 0x7632);
    hi.z = __byte_perm(e4, e5, 0x7632);
    hi.w = __byte_perm(e6, e7, 0x7632);

    const float m0 = u.x - __uint_as_float(e0 & 0xFFFF0000u);
    const float m1 = u.y - __uint_as_float(e1 & 0xFFFF0000u);
    const float m2 = u.z - __uint_as_float(e2 & 0xFFFF0000u);
    const float m3 = u.w - __uint_as_float(e3 & 0xFFFF0000u);
    const float m4 = v.x - __uint_as_float(e4 & 0xFFFF0000u);
    const float m5 = v.y - __uint_as_float(e5 & 0xFFFF0000u);
    const float m6 = v.z - __uint_as_float(e6 & 0xFFFF0000u);
    const float m7 = v.w - __uint_as_float(e7 & 0xFFFF0000u);

    uint4 mi;
    __nv_bfloat162 t;
    t = __floats2bfloat162_rn(m0, m1); mi.x = *(uint32_t*)&t;
    t = __floats2bfloat162_rn(m2, m3); mi.y = *(uint32_t*)&t;
    t = __floats2bfloat162_rn(m4, m5); mi.z = *(uint32_t*)&t;
    t = __floats2bfloat162_rn(m6, m7); mi.w = *(uint32_t*)&t;

    *(uint4*)hiP = hi;
    *(uint4*)miP = mi;
}

// ---------------- transposes -------------------------------------------------
__global__ void transpose1024(const float* __restrict__ in, float* __restrict__ out)
{
    __shared__ float tile[32][33];
    const int x = blockIdx.x*32 + threadIdx.x;
    const int y = blockIdx.y*32 + threadIdx.y;
    #pragma unroll
    for (int j = 0; j < 32; j += 8)
        tile[threadIdx.y + j][threadIdx.x] = in[(size_t)(y + j)*EE + x];
    __syncthreads();
    const int x2 = blockIdx.y*32 + threadIdx.x;
    const int y2 = blockIdx.x*32 + threadIdx.y;
    #pragma unroll
    for (int j = 0; j < 32; j += 8)
        out[(size_t)(y2 + j)*EE + x2] = tile[threadIdx.x][threadIdx.y + j];
}

__global__ void transpose_w1(const float* __restrict__ in, float* __restrict__ out)
{
    __shared__ float tile[32][33];
    const int h = blockIdx.z;
    const size_t base = (size_t)h*DD*DD;
    const int x = blockIdx.x*32 + threadIdx.x;
    const int y = blockIdx.y*32 + threadIdx.y;
    #pragma unroll
    for (int j = 0; j < 32; j += 8)
        tile[threadIdx.y + j][threadIdx.x] = in[base + (size_t)(y + j)*DD + x];
    __syncthreads();
    const int x2 = blockIdx.y*32 + threadIdx.x;
    const int y2 = blockIdx.x*32 + threadIdx.y;
    #pragma unroll
    for (int j = 0; j < 32; j += 8)
        out[base + (size_t)(y2 + j)*DD + x2] = tile[threadIdx.x][threadIdx.y + j];
}

// ---------------- prep_v: one warp per output dot product -------------------
__global__ void prep_v2(const float* __restrict__ W2,
                        const float* __restrict__ b2,
                        const float* __restrict__ watt)
{
    const int w    = threadIdx.x >> 5;
    const int lane = threadIdx.x & 31;
    const float* rp;
    if (blockIdx.x < 128) rp = W2 + (size_t)(blockIdx.x*8 + w)*EE;
    else                  rp = b2 + (size_t)w*EE;
    float s = 0.f;
    #pragma unroll
    for (int j = 0; j < 8; j++) {
        const float4 a  = *(const float4*)(rp   + lane*4 + j*128);
        const float4 wv = *(const float4*)(watt + lane*4 + j*128);
        s = fmaf(a.x, wv.x, fmaf(a.y, wv.y, fmaf(a.z, wv.z, fmaf(a.w, wv.w, s))));
    }
    #pragma unroll
    for (int off = 16; off >= 1; off >>= 1)
        s += __shfl_xor_sync(0xffffffffu, s, off);
    if (lane == 0) {
        if (blockIdx.x < 128) g_V[blockIdx.x*8 + w] = s;
        else                  g_C[w] = s;
    }
}

// ======= split-bf16 3-pass GEMM via mma.m16n8k16 + ldmatrix ==================
// CTA 128x128, 8 warps (2m x 4n), warp tile 64x32; double-buffered smem.
// EPI==0: g_Z = tanh(x @ WezT^T + b_ez)              (K=1024)
// EPI==1: g_H1 = gelu(hln @ W1T[h]^T + b1); logits   (K=128, blockIdx.z = h)
// EPI==2: g_P = g_G @ W2T^T + sum_h scores*b2        (K=1024)
#define PL   6144           // plane bytes (128 * 48)
#define STG  (4*PL)         // stage bytes  (24576)
template<int EPI>
__global__ void __launch_bounds__(256, 2) bf_gemm(
    const float* __restrict__ Aext, const float* __restrict__ Btg,
    const float* __restrict__ bias)
{
    extern __shared__ char smq[];   // 2 * STG = 49152 bytes
    __shared__ float slog[128];

    const int h = (EPI==1) ? (int)blockIdx.z : 0;
    const float* A  = (EPI==0) ? Aext : (EPI==1) ? (g_HLN + h*DD) : g_G;
    const float* Bt = (EPI==1) ? (g_W1T + (size_t)h*DD*DD) : Btg;
    float*       C  = (EPI==0) ? g_Z  : (EPI==1) ? g_H1 : g_P;
    const int LDB = (EPI==1) ? DD : EE;
    const int NKT = (EPI==1) ? 8 : 64;

    const int tid  = threadIdx.x;
    const int wid  = tid >> 5;
    const int lane = tid & 31;
    const int wm   = wid >> 2;      // 0..1
    const int wn   = wid & 3;       // 0..3
    const int rr   = lane & 7;
    const int mq   = lane >> 3;     // 0..3
    const int r    = lane >> 2;     // 0..7
    const int cq   = lane & 3;      // 0..3

    const int m0 = blockIdx.y * 128;
    const int n0 = (EPI==1) ? 0 : blockIdx.x * 128;
    const int colBase = (EPI==1) ? h*DD : n0;

    // producer mapping: thread -> (row 0..127, half 0/1 of 16 k's)
    const int prow = tid >> 1;
    const int phalf = tid & 1;
    const float* srcA = A  + (size_t)(m0 + prow)*EE + phalf*8;
    const float* srcB = Bt + (size_t)(n0 + prow)*LDB + phalf*8;
    char* pdst = smq + prow*48 + phalf*16;

    // consumer ldmatrix lane addresses (within stage)
    const uint32_t sb = smem_u32(smq);
    const uint32_t aAddr = sb + (uint32_t)((wm*64 + (mq&1)*8 + rr)*48 + (mq>>1)*16);
    const uint32_t bAddr = sb + 2u*PL + (uint32_t)((wn*32 + rr)*48 + (mq&1)*16);

    // prologue: chunk 0
    {
        float4 a0 = *(const float4*)(srcA);
        float4 a1 = *(const float4*)(srcA + 4);
        float4 b0 = *(const float4*)(srcB);
        float4 b1 = *(const float4*)(srcB + 4);
        split_store8(a0, a1, pdst,        pdst + PL);
        split_store8(b0, b1, pdst + 2*PL, pdst + 3*PL);
    }
    if (EPI == 1 && tid < 128) slog[tid] = 0.f;
    __syncthreads();

    float acc[4][4][4];
    #pragma unroll
    for (int i = 0; i < 4; i++)
        #pragma unroll
        for (int j = 0; j < 4; j++)
            #pragma unroll
            for (int q = 0; q < 4; q++) acc[i][j][q] = 0.f;

    #pragma unroll 1
    for (int kt = 0; kt < NKT; kt++) {
        float4 pa0, pa1, pb0, pb1;
        if (kt + 1 < NKT) {
            const int ko = (kt + 1) * 16;
            pa0 = *(const float4*)(srcA + ko);
            pa1 = *(const float4*)(srcA + ko + 4);
            pb0 = *(const float4*)(srcB + ko);
            pb1 = *(const float4*)(srcB + ko + 4);
        }

        const uint32_t st = (kt & 1) * (uint32_t)STG;

        uint32_t bh[4][2], bm[4][2];
        #pragma unroll
        for (int ni = 0; ni < 4; ni++) {
            LDSM2(bh[ni][0], bh[ni][1], bAddr + st + ni*384);
            LDSM2(bm[ni][0], bm[ni][1], bAddr + st + PL + ni*384);
        }

        #pragma unroll
        for (int mi = 0; mi < 4; mi++) {
            uint32_t ah[4], am[4];
            LDSM4(ah[0], ah[1], ah[2], ah[3], aAddr + st + mi*768);
            LDSM4(am[0], am[1], am[2], am[3], aAddr + st + PL + mi*768);
            #pragma unroll
            for (int ni = 0; ni < 4; ni++) mmabf(acc[mi][ni], ah, bh[ni]);
            #pragma unroll
            for (int ni = 0; ni < 4; ni++) mmabf(acc[mi][ni], ah, bm[ni]);
            #pragma unroll
            for (int ni = 0; ni < 4; ni++) mmabf(acc[mi][ni], am, bh[ni]);
        }

        if (kt + 1 < NKT) {
            char* nd = pdst + (((kt + 1) & 1) ? STG : 0);
            split_store8(pa0, pa1, nd,        nd + PL);
            split_store8(pb0, pb1, nd + 2*PL, nd + 3*PL);
        }
        __syncthreads();
    }

    // ---------------- epilogue ----------------
    #pragma unroll
    for (int mi = 0; mi < 4; mi++) {
        const int row0 = m0 + wm*64 + mi*16 + r;    // and row0+8
        float sAr[8], sBr[8];
        if (EPI == 2) {
            #pragma unroll
            for (int h2 = 0; h2 < 8; h2++) {
                sAr[h2] = g_SC[(size_t)row0*8 + h2];
                sBr[h2] = g_SC[(size_t)(row0+8)*8 + h2];
            }
        }
        float logitA = 0.f, logitB = 0.f;
        #pragma unroll
        for (int ni = 0; ni < 4; ni++) {
            const int col = colBase + wn*32 + ni*8 + 2*cq;
            float v0 = acc[mi][ni][0], v1 = acc[mi][ni][1];
            float v2 = acc[mi][ni][2], v3 = acc[mi][ni][3];
            if (EPI == 0) {
                v0 = tanhf(v0 + bias[col]);
                v1 = tanhf(v1 + bias[col+1]);
                v2 = tanhf(v2 + bias[col]);
                v3 = tanhf(v3 + bias[col+1]);
            } else if (EPI == 1) {
                const float b0 = bias[col], b1 = bias[col+1];
                v0 += b0; v1 += b1; v2 += b0; v3 += b1;
                v0 = 0.5f*v0*(1.f + erff(v0*0.70710678118654752f));
                v1 = 0.5f*v1*(1.f + erff(v1*0.70710678118654752f));
                v2 = 0.5f*v2*(1.f + erff(v2*0.70710678118654752f));
                v3 = 0.5f*v3*(1.f + erff(v3*0.70710678118654752f));
                const float w0 = g_V[col], w1 = g_V[col+1];
                logitA = fmaf(v0, w0, fmaf(v1, w1, logitA));
                logitB = fmaf(v2, w0, fmaf(v3, w1, logitB));
            } else {
                float b00=0.f, b01=0.f, b10=0.f, b11=0.f;
                #pragma unroll
                for (int h2 = 0; h2 < 8; h2++) {
                    const float w0 = bias[(size_t)h2*EE + col];
                    const float w1 = bias[(size_t)h2*EE + col + 1];
                    b00 = fmaf(sAr[h2], w0, b00);
                    b01 = fmaf(sAr[h2], w1, b01);
                    b10 = fmaf(sBr[h2], w0, b10);
                    b11 = fmaf(sBr[h2], w1, b11);
                }
                v0 += b00; v1 += b01; v2 += b10; v3 += b11;
            }
            float2 p0; p0.x = v0; p0.y = v1;
            float2 p1; p1.x = v2; p1.y = v3;
            *(float2*)(C + (size_t)row0*EE + col)     = p0;
            *(float2*)(C + (size_t)(row0+8)*EE + col) = p1;
        }
        if (EPI == 1) {
            logitA += __shfl_xor_sync(0xffffffffu, logitA, 1);
            logitA += __shfl_xor_sync(0xffffffffu, logitA, 2);
            logitB += __shfl_xor_sync(0xffffffffu, logitB, 1);
            logitB += __shfl_xor_sync(0xffffffffu, logitB, 2);
            if (cq == 0) {
                atomicAdd(&slog[row0 - m0],     logitA);
                atomicAdd(&slog[row0 - m0 + 8], logitB);
            }
        }
    }

    if (EPI == 1) {
        __syncthreads();
        if (tid < 128)
            g_LG[(size_t)(m0 + tid)*8 + h] = slog[tid] + g_C[h];
    }
}

// ---------------- sequential gated scan + per-step LN (folded gate) ---------
// One warp per (b,h); 4 d's per lane. Writes affine LN state to g_ST.
__global__ void scan_kernel(const float* __restrict__ Uh,
                            const float* __restrict__ Uz,
                            const float* __restrict__ Bu,
                            const float* __restrict__ Lg,
                            const float* __restrict__ Lb)
{
    const int bidx = blockIdx.x;
    const int b  = bidx >> 3;
    const int hh = bidx & 7;
    const int lane = threadIdx.x;
    const float G = -1.4426950408889634f;   // -log2(e)

    float A[4], uzs[4], busr[4], bus2[4], lg[4], lb[4];
    #pragma unroll
    for (int i = 0; i < 4; i++) {
        const int d = lane + 32*i;
        const float uh = Uh[(size_t)hh*DD*DD + (size_t)d*(DD+1)];
        const float uz = Uz[(size_t)hh*DD*DD + (size_t)d*(DD+1)];
        const float bu = Bu[hh*DD + d];
        lg[i] = Lg[d];  lb[i] = Lb[d];
        A[i]    = G*uh*lg[i];
        uzs[i]  = G*uz;
        busr[i] = G*bu;                 // step-0 (h=0) variant
        bus2[i] = G*bu + G*uh*lb[i];    // folded lb term for steps >= 1
    }

    const float* zp = g_Z  + (size_t)b*SS*EE + hh*DD + lane;
    float*       sp = g_ST + (size_t)b*SS*EE + hh*DD + lane;

    float z0[4], z1[4], z2[4];
    #pragma unroll
    for (int i = 0; i < 4; i++) z0[i] = zp[32*i];
    #pragma unroll
    for (int i = 0; i < 4; i++) z1[i] = zp[1024 + 32*i];
    #pragma unroll
    for (int i = 0; i < 4; i++) z2[i] = zp[2048 + 32*i];

    float hnP[4];   // normalized (pre-affine) state of previous step
    float oP[4];    // affine state h of previous step

    // -------- peel step 0 (h_prev = 0) --------
    {
        float s1 = 0.f, s2 = 0.f, hn[4];
        #pragma unroll
        for (int i = 0; i < 4; i++) {
            const float e = ex2_(fmaf(z0[i], uzs[i], busr[i]));
            const float u = rcp_(1.f + e);
            const float v = z0[i] - u*z0[i];      // u*0 + (1-u)*z
            hn[i] = v;
            s1 += v;
            s2 = fmaf(v, v, s2);
        }
        r4red2(s1, s2);
        const float mean = s1 * (1.f/128.f);
        const float var  = fmaf(s2, 1.f/128.f, -mean*mean);
        const float rstd = rsqrtf(var + EPSF);
        #pragma unroll
        for (int i = 0; i < 4; i++) {
            hnP[i] = (hn[i] - mean) * rstd;
            oP[i]  = fmaf(hnP[i], lg[i], lb[i]);
            sp[32*i] = oP[i];
        }
    }

    float zz[4];
    #pragma unroll
    for (int i = 0; i < 4; i++) zz[i] = fmaf(z1[i], uzs[i], bus2[i]);
    #pragma unroll
    for (int i = 0; i < 4; i++) { z0[i] = z1[i]; z1[i] = z2[i]; }

    for (int s = 1; s < SS; s++) {
        // ---- critical chain: gate exponent ----
        float e[4], hz[4];
        #pragma unroll
        for (int i = 0; i < 4; i++)
            e[i] = ex2_(fmaf(hnP[i], A[i], zz[i]));
        #pragma unroll
        for (int i = 0; i < 4; i++)
            hz[i] = oP[i] - z0[i];

        // prefetch z[s+2] (in the ex2 shadow)
        #pragma unroll
        for (int i = 0; i < 4; i++) z2[i] = 0.f;
        if (s + 2 < SS) {
            const float* p = zp + (size_t)(s+2)*EE;
            #pragma unroll
            for (int i = 0; i < 4; i++) z2[i] = p[32*i];
        }

        // ---- finish gate + state update ----
        float s1 = 0.f, s2 = 0.f, hn[4];
        #pragma unroll
        for (int i = 0; i < 4; i++) {
            const float u = rcp_(1.f + e[i]);
            const float v = fmaf(u, hz[i], z0[i]);
            hn[i] = v;
            s1 += v;
            s2 = fmaf(v, v, s2);
        }
        // next step's z-part (independent; issues in the reduce shadow)
        float zzn[4];
        #pragma unroll
        for (int i = 0; i < 4; i++) zzn[i] = fmaf(z1[i], uzs[i], bus2[i]);

        r4red2(s1, s2);
        const float mean = s1 * (1.f/128.f);
        const float var  = fmaf(s2, 1.f/128.f, -mean*mean);
        const float rstd = rsqrtf(var + EPSF);
        float* so = sp + (size_t)s*EE;
        #pragma unroll
        for (int i = 0; i < 4; i++) {
            hnP[i] = (hn[i] - mean) * rstd;
            oP[i]  = fmaf(hnP[i], lg[i], lb[i]);
            so[32*i] = oP[i];
        }
        #pragma unroll
        for (int i = 0; i < 4; i++) { z0[i] = z1[i]; z1[i] = z2[i]; zz[i] = zzn[i]; }
    }
}

// ---------------- head_ln ----------------------------------------------------
__global__ void head_ln(const float* __restrict__ OS,
                        const float* __restrict__ fg,
                        const float* __restrict__ fb)
{
    const int r    = blockIdx.x*8 + (threadIdx.x >> 5);
    const int lane = threadIdx.x & 31;
    const int hh   = r & 7;

    const float4 v = ((const float4*)(g_ST + (size_t)r*128))[lane];
    const int d0 = lane*4;
    const float* osb = OS + (size_t)hh*DD*DD;
    const float o0 = osb[(size_t)(d0+0)*(DD+1)];
    const float o1 = osb[(size_t)(d0+1)*(DD+1)];
    const float o2 = osb[(size_t)(d0+2)*(DD+1)];
    const float o3 = osb[(size_t)(d0+3)*(DD+1)];
    const float y0 = v.x*o0, y1 = v.y*o1, y2 = v.z*o2, y3 = v.w*o3;

    float s1 = (y0+y1)+(y2+y3);
    float s2 = fmaf(y0,y0, fmaf(y1,y1, fmaf(y2,y2, y3*y3)));
    #pragma unroll
    for (int off = 16; off >= 1; off >>= 1) {
        s1 += __shfl_xor_sync(0xffffffffu, s1, off);
        s2 += __shfl_xor_sync(0xffffffffu, s2, off);
    }
    const float mean = s1 * (1.f/128.f);
    const float var  = fmaf(s2, 1.f/128.f, -mean*mean);
    const float rstd = rsqrtf(var + EPSF);

    const float4 gv = ((const float4*)(fg + hh*128))[lane];
    const float4 bv = ((const float4*)(fb + hh*128))[lane];
    float4 o;
    o.x = fmaf((y0-mean)*rstd, gv.x, bv.x);
    o.y = fmaf((y1-mean)*rstd, gv.y, bv.y);
    o.z = fmaf((y2-mean)*rstd, gv.z, bv.z);
    o.w = fmaf((y3-mean)*rstd, gv.w, bv.w);
    ((float4*)(g_HLN + (size_t)r*128))[lane] = o;
}

// ---------------- softmax over heads + scale h1 -> g ------------------------
__global__ void softmax_scale()
{
    const int t    = blockIdx.x*8 + (threadIdx.x >> 5);
    const int lane = threadIdx.x & 31;

    float l[8];
    #pragma unroll
    for (int h2 = 0; h2 < 8; h2++) l[h2] = g_LG[(size_t)t*8 + h2];
    float m = l[0];
    #pragma unroll
    for (int h2 = 1; h2 < 8; h2++) m = fmaxf(m, l[h2]);
    float ssum = 0.f;
    #pragma unroll
    for (int h2 = 0; h2 < 8; h2++) { l[h2] = __expf(l[h2]-m); ssum += l[h2]; }
    const float inv = __fdividef(1.f, ssum);

    const float4* in  = (const float4*)(g_H1 + (size_t)t*1024);
    float4*       out = (float4*)      (g_G  + (size_t)t*1024);
    #pragma unroll
    for (int i = 0; i < 8; i++) {
        const float sh = l[i]*inv;
        float4 v = in[i*32 + lane];
        v.x *= sh; v.y *= sh; v.z *= sh; v.w *= sh;
        out[i*32 + lane] = v;
    }
    if (lane < 8) g_SC[(size_t)t*8 + lane] = l[lane]*inv;
}

// ---------------- final LN over E -------------------------------------------
__global__ void final_ln(const float* __restrict__ lg_,
                         const float* __restrict__ lb_,
                         float* __restrict__ out)
{
    __shared__ float sm[16];
    const int t   = blockIdx.x;
    const int tid = threadIdx.x;

    const float4 v = ((const float4*)(g_P + (size_t)t*1024))[tid];
    float s1 = (v.x+v.y)+(v.z+v.w);
    float s2 = fmaf(v.x,v.x, fmaf(v.y,v.y, fmaf(v.z,v.z, v.w*v.w)));
    #pragma unroll
    for (int off = 16; off >= 1; off >>= 1) {
        s1 += __shfl_xor_sync(0xffffffffu, s1, off);
        s2 += __shfl_xor_sync(0xffffffffu, s2, off);
    }
    const int w = tid >> 5, lane = tid & 31;
    if (lane == 0) { sm[w] = s1; sm[8+w] = s2; }
    __syncthreads();
    float t1 = 0.f, t2 = 0.f;
    #pragma unroll
    for (int w2 = 0; w2 < 8; w2++) { t1 += sm[w2]; t2 += sm[8+w2]; }
    const float mean = t1 * (1.f/1024.f);
    const float var  = fmaf(t2, 1.f/1024.f, -mean*mean);
    const float rstd = rsqrtf(var + EPSF);

    const float4 g4 = ((const float4*)lg_)[tid];
    const float4 b4 = ((const float4*)lb_)[tid];
    float4 o;
    o.x = fmaf((v.x-mean)*rstd, g4.x, b4.x);
    o.y = fmaf((v.y-mean)*rstd, g4.y, b4.y);
    o.z = fmaf((v.z-mean)*rstd, g4.z, b4.z);
    o.w = fmaf((v.w-mean)*rstd, g4.w, b4.w);
    ((float4*)(out + (size_t)t*1024))[tid] = o;
}

// ---------------- launch ----------------------------------------------------
#define GEMM_SMEM (2*STG)   // 49152 bytes

extern "C" void kernel_launch(void* const* d_in, const int* in_sizes, int n_in,
                              void* d_out, int out_size)
{
    const float* x      = (const float*)d_in[0];
    const float* W_ez   = (const float*)d_in[1];
    const float* b_ez   = (const float*)d_in[2];
    const float* U_h    = (const float*)d_in[3];
    const float* U_z    = (const float*)d_in[4];
    const float* b_u    = (const float*)d_in[5];
    const float* out_sh = (const float*)d_in[6];
    const float* lns_g  = (const float*)d_in[7];
    const float* lns_b  = (const float*)d_in[8];
    const float* ffln_g = (const float*)d_in[9];
    const float* ffln_b = (const float*)d_in[10];
    const float* ff_W1  = (const float*)d_in[11];
    const float* ff_b1  = (const float*)d_in[12];
    const float* ff_W2  = (const float*)d_in[13];
    const float* ff_b2  = (const float*)d_in[14];
    const float* w_att  = (const float*)d_in[15];
    // d_in[16] = b_att: cancels in softmax
    const float* lno_g  = (const float*)d_in[17];
    const float* lno_b  = (const float*)d_in[18];
    float* out = (float*)d_out;

    cudaFuncSetAttribute(bf_gemm<0>, cudaFuncAttributeMaxDynamicSharedMemorySize, GEMM_SMEM);
    cudaFuncSetAttribute(bf_gemm<1>, cudaFuncAttributeMaxDynamicSharedMemorySize, GEMM_SMEM);
    cudaFuncSetAttribute(bf_gemm<2>, cudaFuncAttributeMaxDynamicSharedMemorySize, GEMM_SMEM);

    float* wezT; cudaGetSymbolAddress((void**)&wezT, g_WezT);
    float* w2T;  cudaGetSymbolAddress((void**)&w2T,  g_W2T);
    float* w1T;  cudaGetSymbolAddress((void**)&w1T,  g_W1T);

    // prep (independent, all fast)
    transpose1024<<<dim3(32,32), dim3(32,8)>>>(W_ez, wezT);
    transpose1024<<<dim3(32,32), dim3(32,8)>>>(ff_W2, w2T);
    transpose_w1<<<dim3(4,4,8), dim3(32,8)>>>(ff_W1, w1T);
    prep_v2<<<129, 256>>>(ff_W2, ff_b2, w_att);

    // z = tanh(x @ W_ez + b_ez)
    bf_gemm<0><<<dim3(EE/128, TT/128), 256, GEMM_SMEM>>>(x, wezT, b_ez);

    // sequential gated scan with per-step LN (folded gate, radix-4 reduce)
    scan_kernel<<<BB*HH, 32>>>(U_h, U_z, b_u, lns_g, lns_b);

    // hln = LN(states * os_diag)
    head_ln<<<TT*HH/8, 256>>>(out_sh, ffln_g, ffln_b);

    // h1 = gelu(hln @ W1[h] + b1[h]); logits in epilogue
    bf_gemm<1><<<dim3(1, TT/128, HH), 256, GEMM_SMEM>>>(nullptr, nullptr, ff_b1);

    // softmax over heads; g = score * h1
    softmax_scale<<<TT/8, 256>>>();

    // weighted = g @ W2 + sum_h s_h*b2
    bf_gemm<2><<<dim3(EE/128, TT/128), 256, GEMM_SMEM>>>(nullptr, w2T, ff_b2);

    // final LN -> output
    final_ln<<<TT, 256>>>(lno_g, lno_b, out);
}

// round 13
// speedup vs baseline: 1.6492x; 1.3466x over previous
#include <cuda_runtime.h>
#include <cuda_bf16.h>
#include <math.h>
#include <stdint.h>

// Problem constants
#define BB 4
#define SS 2048
#define EE 1024
#define HH 8
#define DD 128
#define TT (BB*SS)          // 8192 tokens
#define EPSF 1e-5f

// ---------------- scratch (device globals) ----------------------------------
__device__ float g_Z  [TT*EE];
__device__ float g_ST [TT*EE];
__device__ float g_HLN[TT*EE];
__device__ float g_H1 [TT*EE];
__device__ float g_P  [TT*EE];
__device__ float g_LG [TT*HH];
__device__ float g_SC [TT*HH];
__device__ float g_V  [HH*DD];
__device__ float g_C  [HH];
__device__ float g_WezT[EE*EE];    // W_ez^T  [n][k]
__device__ float g_W2T [EE*EE];    // ff_W2^T [n][k]
__device__ float g_W1T [HH*DD*DD]; // per-head W1^T [h][e][d]

// ---------------- helpers ----------------------------------------------------
__device__ __forceinline__ uint32_t smem_u32(const void* p) {
    uint32_t a;
    asm("{ .reg .u64 t; cvta.to.shared.u64 t, %1; cvt.u32.u64 %0, t; }"
        : "=r"(a) : "l"(p));
    return a;
}
#define LDSM4(r0, r1, r2, r3, a) \
    asm volatile("ldmatrix.sync.aligned.m8n8.x4.shared.b16 {%0,%1,%2,%3}, [%4];" \
        : "=r"(r0), "=r"(r1), "=r"(r2), "=r"(r3) : "r"(a))
#define LDSM2(r0, r1, a) \
    asm volatile("ldmatrix.sync.aligned.m8n8.x2.shared.b16 {%0,%1}, [%2];" \
        : "=r"(r0), "=r"(r1) : "r"(a))

__device__ __forceinline__ void mmabf(float* c, const uint32_t* a, const uint32_t* b) {
    asm volatile("mma.sync.aligned.m16n8k16.row.col.f32.bf16.bf16.f32 "
        "{%0,%1,%2,%3}, {%4,%5,%6,%7}, {%8,%9}, {%0,%1,%2,%3};"
        : "+f"(c[0]), "+f"(c[1]), "+f"(c[2]), "+f"(c[3])
        : "r"(a[0]), "r"(a[1]), "r"(a[2]), "r"(a[3]), "r"(b[0]), "r"(b[1]));
}

// split 8 fp32 into hi (truncated bf16) + mid (bf16 residual), packed bf16x2
__device__ __forceinline__ void split_store8(float4 u, float4 v,
                                             char* hiP, char* miP)
{
    const uint32_t e0 = __float_as_uint(u.x), e1 = __float_as_uint(u.y);
    const uint32_t e2 = __float_as_uint(u.z), e3 = __float_as_uint(u.w);
    const uint32_t e4 = __float_as_uint(v.x), e5 = __float_as_uint(v.y);
    const uint32_t e6 = __float_as_uint(v.z), e7 = __float_as_uint(v.w);

    uint4 hi;
    hi.x = __byte_perm(e0, e1, 0x7632);
    hi.y = __byte_perm(e2, e3, 0x7632);
    hi.z = __byte_perm(e4, e5, 0x7632);
    hi.w = __byte_perm(e6, e7, 0x7632);

    const float m0 = u.x - __uint_as_float(e0 & 0xFFFF0000u);
    const float m1 = u.y - __uint_as_float(e1 & 0xFFFF0000u);
    const float m2 = u.z - __uint_as_float(e2 & 0xFFFF0000u);
    const float m3 = u.w - __uint_as_float(e3 & 0xFFFF0000u);
    const float m4 = v.x - __uint_as_float(e4 & 0xFFFF0000u);
    const float m5 = v.y - __uint_as_float(e5 & 0xFFFF0000u);
    const float m6 = v.z - __uint_as_float(e6 & 0xFFFF0000u);
    const float m7 = v.w - __uint_as_float(e7 & 0xFFFF0000u);

    uint4 mi;
    __nv_bfloat162 t;
    t = __floats2bfloat162_rn(m0, m1); mi.x = *(uint32_t*)&t;
    t = __floats2bfloat162_rn(m2, m3); mi.y = *(uint32_t*)&t;
    t = __floats2bfloat162_rn(m4, m5); mi.z = *(uint32_t*)&t;
    t = __floats2bfloat162_rn(m6, m7); mi.w = *(uint32_t*)&t;

    *(uint4*)hiP = hi;
    *(uint4*)miP = mi;
}

// ---------------- transposes -------------------------------------------------
__global__ void transpose1024(const float* __restrict__ in, float* __restrict__ out)
{
    __shared__ float tile[32][33];
    const int x = blockIdx.x*32 + threadIdx.x;
    const int y = blockIdx.y*32 + threadIdx.y;
    #pragma unroll
    for (int j = 0; j < 32; j += 8)
        tile[threadIdx.y + j][threadIdx.x] = in[(size_t)(y + j)*EE + x];
    __syncthreads();
    const int x2 = blockIdx.y*32 + threadIdx.x;
    const int y2 = blockIdx.x*32 + threadIdx.y;
    #pragma unroll
    for (int j = 0; j < 32; j += 8)
        out[(size_t)(y2 + j)*EE + x2] = tile[threadIdx.x][threadIdx.y + j];
}

__global__ void transpose_w1(const float* __restrict__ in, float* __restrict__ out)
{
    __shared__ float tile[32][33];
    const int h = blockIdx.z;
    const size_t base = (size_t)h*DD*DD;
    const int x = blockIdx.x*32 + threadIdx.x;
    const int y = blockIdx.y*32 + threadIdx.y;
    #pragma unroll
    for (int j = 0; j < 32; j += 8)
        tile[threadIdx.y + j][threadIdx.x] = in[base + (size_t)(y + j)*DD + x];
    __syncthreads();
    const int x2 = blockIdx.y*32 + threadIdx.x;
    const int y2 = blockIdx.x*32 + threadIdx.y;
    #pragma unroll
    for (int j = 0; j < 32; j += 8)
        out[base + (size_t)(y2 + j)*DD + x2] = tile[threadIdx.x][threadIdx.y + j];
}

// ---------------- prep_v: one warp per output dot product -------------------
__global__ void prep_v2(const float* __restrict__ W2,
                        const float* __restrict__ b2,
                        const float* __restrict__ watt)
{
    const int w    = threadIdx.x >> 5;
    const int lane = threadIdx.x & 31;
    const float* rp;
    if (blockIdx.x < 128) rp = W2 + (size_t)(blockIdx.x*8 + w)*EE;
    else                  rp = b2 + (size_t)w*EE;
    float s = 0.f;
    #pragma unroll
    for (int j = 0; j < 8; j++) {
        const float4 a  = *(const float4*)(rp   + lane*4 + j*128);
        const float4 wv = *(const float4*)(watt + lane*4 + j*128);
        s = fmaf(a.x, wv.x, fmaf(a.y, wv.y, fmaf(a.z, wv.z, fmaf(a.w, wv.w, s))));
    }
    #pragma unroll
    for (int off = 16; off >= 1; off >>= 1)
        s += __shfl_xor_sync(0xffffffffu, s, off);
    if (lane == 0) {
        if (blockIdx.x < 128) g_V[blockIdx.x*8 + w] = s;
        else                  g_C[w] = s;
    }
}

// ======= split-bf16 3-pass GEMM via mma.m16n8k16 + ldmatrix ==================
// CTA 128x128, 8 warps (2m x 4n), warp tile 64x32; double-buffered smem.
// EPI==0: g_Z = tanh(x @ WezT^T + b_ez)              (K=1024)
// EPI==1: g_H1 = gelu(hln @ W1T[h]^T + b1); logits   (K=128, blockIdx.z = h)
// EPI==2: g_P = (score*g_H1) @ W2T^T + sum_h sc*b2   (K=1024, score in producer)
#define PL   6144           // plane bytes (128 * 48)
#define STG  (4*PL)         // stage bytes  (24576)
template<int EPI>
__global__ void __launch_bounds__(256, 2) bf_gemm(
    const float* __restrict__ Aext, const float* __restrict__ Btg,
    const float* __restrict__ bias)
{
    extern __shared__ char smq[];   // 2 * STG = 49152 bytes
    __shared__ float slog[128];

    const int h = (EPI==1) ? (int)blockIdx.z : 0;
    const float* A  = (EPI==0) ? Aext : (EPI==1) ? (g_HLN + h*DD) : g_H1;
    const float* Bt = (EPI==1) ? (g_W1T + (size_t)h*DD*DD) : Btg;
    float*       C  = (EPI==0) ? g_Z  : (EPI==1) ? g_H1 : g_P;
    const int LDB = (EPI==1) ? DD : EE;
    const int NKT = (EPI==1) ? 8 : 64;

    const int tid  = threadIdx.x;
    const int wid  = tid >> 5;
    const int lane = tid & 31;
    const int wm   = wid >> 2;      // 0..1
    const int wn   = wid & 3;       // 0..3
    const int rr   = lane & 7;
    const int mq   = lane >> 3;     // 0..3
    const int r    = lane >> 2;     // 0..7
    const int cq   = lane & 3;      // 0..3

    const int m0 = blockIdx.y * 128;
    const int n0 = (EPI==1) ? 0 : blockIdx.x * 128;
    const int colBase = (EPI==1) ? h*DD : n0;

    // producer mapping: thread -> (row 0..127, half 0/1 of 16 k's)
    const int prow = tid >> 1;
    const int phalf = tid & 1;
    const float* srcA = A  + (size_t)(m0 + prow)*EE + phalf*8;
    const float* srcB = Bt + (size_t)(n0 + prow)*LDB + phalf*8;
    char* pdst = smq + prow*48 + phalf*16;

    // per-row softmax scores for the producer (EPI==2 only)
    float sc8[8];
    if (EPI == 2) {
        const float4 s0 = *(const float4*)(g_SC + (size_t)(m0 + prow)*8);
        const float4 s1 = *(const float4*)(g_SC + (size_t)(m0 + prow)*8 + 4);
        sc8[0]=s0.x; sc8[1]=s0.y; sc8[2]=s0.z; sc8[3]=s0.w;
        sc8[4]=s1.x; sc8[5]=s1.y; sc8[6]=s1.z; sc8[7]=s1.w;
    }

    // consumer ldmatrix lane addresses (within stage)
    const uint32_t sb = smem_u32(smq);
    const uint32_t aAddr = sb + (uint32_t)((wm*64 + (mq&1)*8 + rr)*48 + (mq>>1)*16);
    const uint32_t bAddr = sb + 2u*PL + (uint32_t)((wn*32 + rr)*48 + (mq&1)*16);

    // prologue: chunk 0
    {
        float4 a0 = *(const float4*)(srcA);
        float4 a1 = *(const float4*)(srcA + 4);
        if (EPI == 2) {
            const float s = sc8[0];
            a0.x*=s; a0.y*=s; a0.z*=s; a0.w*=s;
            a1.x*=s; a1.y*=s; a1.z*=s; a1.w*=s;
        }
        float4 b0 = *(const float4*)(srcB);
        float4 b1 = *(const float4*)(srcB + 4);
        split_store8(a0, a1, pdst,        pdst + PL);
        split_store8(b0, b1, pdst + 2*PL, pdst + 3*PL);
    }
    if (EPI == 1 && tid < 128) slog[tid] = 0.f;
    __syncthreads();

    float acc[4][4][4];
    #pragma unroll
    for (int i = 0; i < 4; i++)
        #pragma unroll
        for (int j = 0; j < 4; j++)
            #pragma unroll
            for (int q = 0; q < 4; q++) acc[i][j][q] = 0.f;

    #pragma unroll 1
    for (int kt = 0; kt < NKT; kt++) {
        float4 pa0, pa1, pb0, pb1;
        if (kt + 1 < NKT) {
            const int ko = (kt + 1) * 16;
            pa0 = *(const float4*)(srcA + ko);
            pa1 = *(const float4*)(srcA + ko + 4);
            pb0 = *(const float4*)(srcB + ko);
            pb1 = *(const float4*)(srcB + ko + 4);
            if (EPI == 2) {
                const float s = sc8[(kt + 1) >> 3];
                pa0.x*=s; pa0.y*=s; pa0.z*=s; pa0.w*=s;
                pa1.x*=s; pa1.y*=s; pa1.z*=s; pa1.w*=s;
            }
        }

        const uint32_t st = (kt & 1) * (uint32_t)STG;

        uint32_t bh[4][2], bm[4][2];
        #pragma unroll
        for (int ni = 0; ni < 4; ni++) {
            LDSM2(bh[ni][0], bh[ni][1], bAddr + st + ni*384);
            LDSM2(bm[ni][0], bm[ni][1], bAddr + st + PL + ni*384);
        }

        #pragma unroll
        for (int mi = 0; mi < 4; mi++) {
            uint32_t ah[4], am[4];
            LDSM4(ah[0], ah[1], ah[2], ah[3], aAddr + st + mi*768);
            LDSM4(am[0], am[1], am[2], am[3], aAddr + st + PL + mi*768);
            #pragma unroll
            for (int ni = 0; ni < 4; ni++) mmabf(acc[mi][ni], ah, bh[ni]);
            #pragma unroll
            for (int ni = 0; ni < 4; ni++) mmabf(acc[mi][ni], ah, bm[ni]);
            #pragma unroll
            for (int ni = 0; ni < 4; ni++) mmabf(acc[mi][ni], am, bh[ni]);
        }

        if (kt + 1 < NKT) {
            char* nd = pdst + (((kt + 1) & 1) ? STG : 0);
            split_store8(pa0, pa1, nd,        nd + PL);
            split_store8(pb0, pb1, nd + 2*PL, nd + 3*PL);
        }
        __syncthreads();
    }

    // ---------------- epilogue ----------------
    #pragma unroll
    for (int mi = 0; mi < 4; mi++) {
        const int row0 = m0 + wm*64 + mi*16 + r;    // and row0+8
        float sAr[8], sBr[8];
        if (EPI == 2) {
            #pragma unroll
            for (int h2 = 0; h2 < 8; h2++) {
                sAr[h2] = g_SC[(size_t)row0*8 + h2];
                sBr[h2] = g_SC[(size_t)(row0+8)*8 + h2];
            }
        }
        float logitA = 0.f, logitB = 0.f;
        #pragma unroll
        for (int ni = 0; ni < 4; ni++) {
            const int col = colBase + wn*32 + ni*8 + 2*cq;
            float v0 = acc[mi][ni][0], v1 = acc[mi][ni][1];
            float v2 = acc[mi][ni][2], v3 = acc[mi][ni][3];
            if (EPI == 0) {
                v0 = tanhf(v0 + bias[col]);
                v1 = tanhf(v1 + bias[col+1]);
                v2 = tanhf(v2 + bias[col]);
                v3 = tanhf(v3 + bias[col+1]);
            } else if (EPI == 1) {
                const float b0 = bias[col], b1 = bias[col+1];
                v0 += b0; v1 += b1; v2 += b0; v3 += b1;
                v0 = 0.5f*v0*(1.f + erff(v0*0.70710678118654752f));
                v1 = 0.5f*v1*(1.f + erff(v1*0.70710678118654752f));
                v2 = 0.5f*v2*(1.f + erff(v2*0.70710678118654752f));
                v3 = 0.5f*v3*(1.f + erff(v3*0.70710678118654752f));
                const float w0 = g_V[col], w1 = g_V[col+1];
                logitA = fmaf(v0, w0, fmaf(v1, w1, logitA));
                logitB = fmaf(v2, w0, fmaf(v3, w1, logitB));
            } else {
                float b00=0.f, b01=0.f, b10=0.f, b11=0.f;
                #pragma unroll
                for (int h2 = 0; h2 < 8; h2++) {
                    const float w0 = bias[(size_t)h2*EE + col];
                    const float w1 = bias[(size_t)h2*EE + col + 1];
                    b00 = fmaf(sAr[h2], w0, b00);
                    b01 = fmaf(sAr[h2], w1, b01);
                    b10 = fmaf(sBr[h2], w0, b10);
                    b11 = fmaf(sBr[h2], w1, b11);
                }
                v0 += b00; v1 += b01; v2 += b10; v3 += b11;
            }
            float2 p0; p0.x = v0; p0.y = v1;
            float2 p1; p1.x = v2; p1.y = v3;
            *(float2*)(C + (size_t)row0*EE + col)     = p0;
            *(float2*)(C + (size_t)(row0+8)*EE + col) = p1;
        }
        if (EPI == 1) {
            logitA += __shfl_xor_sync(0xffffffffu, logitA, 1);
            logitA += __shfl_xor_sync(0xffffffffu, logitA, 2);
            logitB += __shfl_xor_sync(0xffffffffu, logitB, 1);
            logitB += __shfl_xor_sync(0xffffffffu, logitB, 2);
            if (cq == 0) {
                atomicAdd(&slog[row0 - m0],     logitA);
                atomicAdd(&slog[row0 - m0 + 8], logitB);
            }
        }
    }

    if (EPI == 1) {
        __syncthreads();
        if (tid < 128)
            g_LG[(size_t)(m0 + tid)*8 + h] = slog[tid] + g_C[h];
    }
}

// ---------------- sequential gated scan + per-step LN (R7-proven) -----------
__global__ void scan_kernel(const float* __restrict__ Uh,
                            const float* __restrict__ Uz,
                            const float* __restrict__ Bu,
                            const float* __restrict__ Lg,
                            const float* __restrict__ Lb)
{
    const int bidx = blockIdx.x;
    const int b  = bidx >> 3;
    const int hh = bidx & 7;
    const int lane = threadIdx.x;

    float uh[4], uz[4], bu[4], lg[4], lb[4], h[4];
    #pragma unroll
    for (int i = 0; i < 4; i++) {
        const int d = lane + 32*i;
        uh[i] = Uh[(size_t)hh*DD*DD + (size_t)d*(DD+1)];
        uz[i] = Uz[(size_t)hh*DD*DD + (size_t)d*(DD+1)];
        bu[i] = Bu[hh*DD + d];
        lg[i] = Lg[d];
        lb[i] = Lb[d];
        h[i]  = 0.f;
    }

    const float* zp = g_Z  + (size_t)b*SS*EE + hh*DD + lane;
    float*       sp = g_ST + (size_t)b*SS*EE + hh*DD + lane;

    float z0[4], z1[4], zz[4];
    #pragma unroll
    for (int i = 0; i < 4; i++) z0[i] = zp[32*i];
    #pragma unroll
    for (int i = 0; i < 4; i++) z1[i] = zp[1024 + 32*i];
    #pragma unroll
    for (int i = 0; i < 4; i++) zz[i] = fmaf(z0[i], uz[i], bu[i]);

    for (int s = 0; s < SS; s++) {
        float z2[4] = {0.f, 0.f, 0.f, 0.f};
        if (s + 2 < SS) {
            const float* p = zp + (size_t)(s+2)*EE;
            #pragma unroll
            for (int i = 0; i < 4; i++) z2[i] = p[32*i];
        }
        float hn[4];
        float s1 = 0.f, s2 = 0.f;
        #pragma unroll
        for (int i = 0; i < 4; i++) {
            float t = fmaf(h[i], uh[i], zz[i]);
            float u = __fdividef(1.f, 1.f + __expf(-t));
            float v = fmaf(u, h[i] - z0[i], z0[i]);
            hn[i] = v;
            s1 += v;
            s2 = fmaf(v, v, s2);
        }
        float zzn[4];
        #pragma unroll
        for (int i = 0; i < 4; i++) zzn[i] = fmaf(z1[i], uz[i], bu[i]);
        #pragma unroll
        for (int off = 16; off >= 1; off >>= 1) {
            s1 += __shfl_xor_sync(0xffffffffu, s1, off);
            s2 += __shfl_xor_sync(0xffffffffu, s2, off);
        }
        const float mean = s1 * (1.f/128.f);
        const float var  = fmaf(s2, 1.f/128.f, -mean*mean);
        const float rstd = rsqrtf(var + EPSF);
        float* so = sp + (size_t)s*EE;
        #pragma unroll
        for (int i = 0; i < 4; i++) {
            float o = fmaf((hn[i] - mean) * rstd, lg[i], lb[i]);
            h[i] = o;
            so[32*i] = o;
        }
        #pragma unroll
        for (int i = 0; i < 4; i++) { z0[i] = z1[i]; z1[i] = z2[i]; zz[i] = zzn[i]; }
    }
}

// ---------------- head_ln ----------------------------------------------------
__global__ void head_ln(const float* __restrict__ OS,
                        const float* __restrict__ fg,
                        const float* __restrict__ fb)
{
    const int r    = blockIdx.x*8 + (threadIdx.x >> 5);
    const int lane = threadIdx.x & 31;
    const int hh   = r & 7;

    const float4 v = ((const float4*)(g_ST + (size_t)r*128))[lane];
    const int d0 = lane*4;
    const float* osb = OS + (size_t)hh*DD*DD;
    const float o0 = osb[(size_t)(d0+0)*(DD+1)];
    const float o1 = osb[(size_t)(d0+1)*(DD+1)];
    const float o2 = osb[(size_t)(d0+2)*(DD+1)];
    const float o3 = osb[(size_t)(d0+3)*(DD+1)];
    const float y0 = v.x*o0, y1 = v.y*o1, y2 = v.z*o2, y3 = v.w*o3;

    float s1 = (y0+y1)+(y2+y3);
    float s2 = fmaf(y0,y0, fmaf(y1,y1, fmaf(y2,y2, y3*y3)));
    #pragma unroll
    for (int off = 16; off >= 1; off >>= 1) {
        s1 += __shfl_xor_sync(0xffffffffu, s1, off);
        s2 += __shfl_xor_sync(0xffffffffu, s2, off);
    }
    const float mean = s1 * (1.f/128.f);
    const float var  = fmaf(s2, 1.f/128.f, -mean*mean);
    const float rstd = rsqrtf(var + EPSF);

    const float4 gv = ((const float4*)(fg + hh*128))[lane];
    const float4 bv = ((const float4*)(fb + hh*128))[lane];
    float4 o;
    o.x = fmaf((y0-mean)*rstd, gv.x, bv.x);
    o.y = fmaf((y1-mean)*rstd, gv.y, bv.y);
    o.z = fmaf((y2-mean)*rstd, gv.z, bv.z);
    o.w = fmaf((y3-mean)*rstd, gv.w, bv.w);
    ((float4*)(g_HLN + (size_t)r*128))[lane] = o;
}

// ---------------- softmax over heads (logits -> scores only) ----------------
__global__ void softmax_only()
{
    const int t = blockIdx.x*256 + threadIdx.x;
    const float4 a = *(const float4*)(g_LG + (size_t)t*8);
    const float4 b = *(const float4*)(g_LG + (size_t)t*8 + 4);
    float l[8] = {a.x, a.y, a.z, a.w, b.x, b.y, b.z, b.w};
    float m = l[0];
    #pragma unroll
    for (int h2 = 1; h2 < 8; h2++) m = fmaxf(m, l[h2]);
    float ssum = 0.f;
    #pragma unroll
    for (int h2 = 0; h2 < 8; h2++) { l[h2] = __expf(l[h2]-m); ssum += l[h2]; }
    const float inv = __fdividef(1.f, ssum);
    float4 o0, o1;
    o0.x = l[0]*inv; o0.y = l[1]*inv; o0.z = l[2]*inv; o0.w = l[3]*inv;
    o1.x = l[4]*inv; o1.y = l[5]*inv; o1.z = l[6]*inv; o1.w = l[7]*inv;
    *(float4*)(g_SC + (size_t)t*8)     = o0;
    *(float4*)(g_SC + (size_t)t*8 + 4) = o1;
}

// ---------------- final LN over E -------------------------------------------
__global__ void final_ln(const float* __restrict__ lg_,
                         const float* __restrict__ lb_,
                         float* __restrict__ out)
{
    __shared__ float sm[16];
    const int t   = blockIdx.x;
    const int tid = threadIdx.x;

    const float4 v = ((const float4*)(g_P + (size_t)t*1024))[tid];
    float s1 = (v.x+v.y)+(v.z+v.w);
    float s2 = fmaf(v.x,v.x, fmaf(v.y,v.y, fmaf(v.z,v.z, v.w*v.w)));
    #pragma unroll
    for (int off = 16; off >= 1; off >>= 1) {
        s1 += __shfl_xor_sync(0xffffffffu, s1, off);
        s2 += __shfl_xor_sync(0xffffffffu, s2, off);
    }
    const int w = tid >> 5, lane = tid & 31;
    if (lane == 0) { sm[w] = s1; sm[8+w] = s2; }
    __syncthreads();
    float t1 = 0.f, t2 = 0.f;
    #pragma unroll
    for (int w2 = 0; w2 < 8; w2++) { t1 += sm[w2]; t2 += sm[8+w2]; }
    const float mean = t1 * (1.f/1024.f);
    const float var  = fmaf(t2, 1.f/1024.f, -mean*mean);
    const float rstd = rsqrtf(var + EPSF);

    const float4 g4 = ((const float4*)lg_)[tid];
    const float4 b4 = ((const float4*)lb_)[tid];
    float4 o;
    o.x = fmaf((v.x-mean)*rstd, g4.x, b4.x);
    o.y = fmaf((v.y-mean)*rstd, g4.y, b4.y);
    o.z = fmaf((v.z-mean)*rstd, g4.z, b4.z);
    o.w = fmaf((v.w-mean)*rstd, g4.w, b4.w);
    ((float4*)(out + (size_t)t*1024))[tid] = o;
}

// ---------------- launch ----------------------------------------------------
#define GEMM_SMEM (2*STG)   // 49152 bytes

extern "C" void kernel_launch(void* const* d_in, const int* in_sizes, int n_in,
                              void* d_out, int out_size)
{
    const float* x      = (const float*)d_in[0];
    const float* W_ez   = (const float*)d_in[1];
    const float* b_ez   = (const float*)d_in[2];
    const float* U_h    = (const float*)d_in[3];
    const float* U_z    = (const float*)d_in[4];
    const float* b_u    = (const float*)d_in[5];
    const float* out_sh = (const float*)d_in[6];
    const float* lns_g  = (const float*)d_in[7];
    const float* lns_b  = (const float*)d_in[8];
    const float* ffln_g = (const float*)d_in[9];
    const float* ffln_b = (const float*)d_in[10];
    const float* ff_W1  = (const float*)d_in[11];
    const float* ff_b1  = (const float*)d_in[12];
    const float* ff_W2  = (const float*)d_in[13];
    const float* ff_b2  = (const float*)d_in[14];
    const float* w_att  = (const float*)d_in[15];
    // d_in[16] = b_att: cancels in softmax
    const float* lno_g  = (const float*)d_in[17];
    const float* lno_b  = (const float*)d_in[18];
    float* out = (float*)d_out;

    cudaFuncSetAttribute(bf_gemm<0>, cudaFuncAttributeMaxDynamicSharedMemorySize, GEMM_SMEM);
    cudaFuncSetAttribute(bf_gemm<1>, cudaFuncAttributeMaxDynamicSharedMemorySize, GEMM_SMEM);
    cudaFuncSetAttribute(bf_gemm<2>, cudaFuncAttributeMaxDynamicSharedMemorySize, GEMM_SMEM);

    float* wezT; cudaGetSymbolAddress((void**)&wezT, g_WezT);
    float* w2T;  cudaGetSymbolAddress((void**)&w2T,  g_W2T);
    float* w1T;  cudaGetSymbolAddress((void**)&w1T,  g_W1T);

    // prep (independent, all fast)
    transpose1024<<<dim3(32,32), dim3(32,8)>>>(W_ez, wezT);
    transpose1024<<<dim3(32,32), dim3(32,8)>>>(ff_W2, w2T);
    transpose_w1<<<dim3(4,4,8), dim3(32,8)>>>(ff_W1, w1T);
    prep_v2<<<129, 256>>>(ff_W2, ff_b2, w_att);

    // z = tanh(x @ W_ez + b_ez)
    bf_gemm<0><<<dim3(EE/128, TT/128), 256, GEMM_SMEM>>>(x, wezT, b_ez);

    // sequential gated scan with per-step LN (proven R7 version)
    scan_kernel<<<BB*HH, 32>>>(U_h, U_z, b_u, lns_g, lns_b);

    // hln = LN(states * os_diag)
    head_ln<<<TT*HH/8, 256>>>(out_sh, ffln_g, ffln_b);

    // h1 = gelu(hln @ W1[h] + b1[h]); logits in epilogue
    bf_gemm<1><<<dim3(1, TT/128, HH), 256, GEMM_SMEM>>>(nullptr, nullptr, ff_b1);

    // softmax over heads (scores only; scaling folded into GEMM2 producer)
    softmax_only<<<TT/256, 256>>>();

    // weighted = (score*h1) @ W2 + sum_h s_h*b2
    bf_gemm<2><<<dim3(EE/128, TT/128), 256, GEMM_SMEM>>>(nullptr, w2T, ff_b2);

    // final LN -> output
    final_ln<<<TT, 256>>>(lno_g, lno_b, out);
}